// round 10
// baseline (speedup 1.0000x reference)
#include <cuda_runtime.h>

#define NP     32768
#define HIDN   100
#define NSTEPS 100

typedef unsigned long long u64;

__device__ __forceinline__ u64 bcast2(float x) {
    u64 r; asm("mov.b64 %0, {%1, %1};" : "=l"(r) : "f"(x)); return r;
}
__device__ __forceinline__ u64 pack2(float x, float y) {
    u64 r; asm("mov.b64 %0, {%1, %2};" : "=l"(r) : "f"(x), "f"(y)); return r;
}
__device__ __forceinline__ void ffma2(u64& d, u64 a, u64 b) {
    asm("fma.rn.f32x2 %0, %1, %2, %0;" : "+l"(d) : "l"(a), "l"(b));
}
__device__ __forceinline__ float2 unpk(u64 v) {
    float2 r; asm("mov.b64 {%0, %1}, %2;" : "=f"(r.x), "=f"(r.y) : "l"(v)); return r;
}

// ---------------------------------------------------------------------------
// Encoder: h1 = swish(x@We1+be1); h2 = swish(h1@We2+be2);
//          mu_zx = h2@Wmu+bmu ; log_t_zx = h2@Wlt+blt
// ---------------------------------------------------------------------------
__global__ void __launch_bounds__(128) encoder_kernel(
    const float* __restrict__ x,
    const float* __restrict__ We1, const float* __restrict__ be1,
    const float* __restrict__ We2, const float* __restrict__ be2,
    const float* __restrict__ Wmu, const float* __restrict__ bmu,
    const float* __restrict__ Wlt, const float* __restrict__ blt,
    float* __restrict__ out)
{
    extern __shared__ float sm[];
    float* sWe2 = sm;             // 10000
    float* sWe1 = sm + 10000;     // 300
    float* sbe1 = sm + 10300;     // 100
    float* sbe2 = sm + 10400;     // 100
    float* sWmu = sm + 10500;     // 200
    float* sWlt = sm + 10700;     // 100
    float* sh1  = sm + 10800;     // 128*101

    const int tid = threadIdx.x;
    for (int i = tid; i < HIDN * HIDN; i += 128) sWe2[i] = We2[i];
    for (int i = tid; i < 3 * HIDN; i += 128)    sWe1[i] = We1[i];
    if (tid < HIDN) {
        sbe1[tid] = be1[tid];
        sbe2[tid] = be2[tid];
        sWlt[tid] = Wlt[tid];
    }
    for (int i = tid; i < HIDN * 2; i += 128) sWmu[i] = Wmu[i];
    __syncthreads();

    const int p = blockIdx.x * 128 + tid;
    const float x0 = x[3 * p + 0];
    const float x1 = x[3 * p + 1];
    const float x2 = x[3 * p + 2];

    float* h1 = sh1 + tid * (HIDN + 1);

    #pragma unroll 4
    for (int k = 0; k < HIDN; k++) {
        float a = sbe1[k];
        a = fmaf(x0, sWe1[k], a);
        a = fmaf(x1, sWe1[HIDN + k], a);
        a = fmaf(x2, sWe1[2 * HIDN + k], a);
        float sig = __fdividef(1.f, 1.f + __expf(-a));
        h1[k] = a * sig;
    }

    float mu0 = bmu[0], mu1 = bmu[1], ltv = blt[0];
    for (int k = 0; k < HIDN; k++) {
        float a = sbe2[k];
        const float* w = sWe2 + k;
        #pragma unroll 4
        for (int j = 0; j < HIDN; j++)
            a = fmaf(h1[j], w[j * HIDN], a);
        float sig = __fdividef(1.f, 1.f + __expf(-a));
        float h2 = a * sig;
        mu0 = fmaf(h2, sWmu[2 * k + 0], mu0);
        mu1 = fmaf(h2, sWmu[2 * k + 1], mu1);
        ltv = fmaf(h2, sWlt[k], ltv);
    }

    out[8 * NP + 2 * p + 0] = mu0;
    out[8 * NP + 2 * p + 1] = mu1;
    out[10 * NP + p]        = ltv;
}

// ---------------------------------------------------------------------------
// SDE kernel v4: 1 thread/point; 30 moment accumulators packed as 15
// fp32x2 (FFMA2) accumulators over head pairs. Per-lane arithmetic is
// bit-identical to the scalar version.
//
// Head order i = {wmu0, wmu1, wmu2, ws0, ws1, ws2}; pairs (0,1),(2,3),(4,5).
// accJ0[p] = (J[2p][0], J[2p+1][0]); accJ1: component 1;
// accB0/1/2[p]: Bm q=0,1,2 likewise.
// ---------------------------------------------------------------------------
__global__ void __launch_bounds__(128) sde_kernel(
    const float* __restrict__ Wd1,  const float* __restrict__ bd1,
    const float* __restrict__ Wdmu, const float* __restrict__ bdmu,
    const float* __restrict__ Wds,  const float* __restrict__ bds,
    const float* __restrict__ b_muz, const float* __restrict__ b_ltz,
    const float* __restrict__ noise,
    float* __restrict__ out)
{
    // tAct = {u0, u1, b, u0*u0}; tU = {u0*u1, u1*u1};
    // tW = {(w0,w1),(w2,w3)} packed b64; tW45 = (w4,w5) packed b64.
    __shared__ float4 tAct[HIDN];
    __shared__ float2 tU[HIDN];
    __shared__ ulonglong2 tW[HIDN];
    __shared__ u64 tW45[HIDN];

    const int tid = threadIdx.x;
    for (int j = tid; j < HIDN; j += 128) {
        float u0 = Wd1[j];
        float u1 = Wd1[HIDN + j];
        float b  = bd1[j];
        tAct[j] = make_float4(u0, u1, b, u0 * u0);
        tU[j]   = make_float2(u0 * u1, u1 * u1);
        float w0 = Wdmu[j * 3 + 0], w1 = Wdmu[j * 3 + 1], w2 = Wdmu[j * 3 + 2];
        float w3 = Wds[j * 3 + 0],  w4 = Wds[j * 3 + 1],  w5 = Wds[j * 3 + 2];
        ulonglong2 wp; wp.x = pack2(w0, w1); wp.y = pack2(w2, w3);
        tW[j]   = wp;
        tW45[j] = pack2(w4, w5);
    }
    __syncthreads();

    const int p = blockIdx.x * 128 + tid;

    float z0 = out[8 * NP + 2 * p + 0];
    float z1 = out[8 * NP + 2 * p + 1];
    const float ltv  = out[10 * NP + p];
    const float sqdt = sqrtf(__expf(2.f * ltv) * (1.0f / NSTEPS));

    const float2* __restrict__ noise2 = (const float2*)noise;

    for (int s = 0; s < NSTEPS; s++) {
        // prefetch this step's noise early: overlap LDG with the j-loop
        const float2 nz = noise2[s * NP + p];

        u64 accJ0[3], accJ1[3], accB0[3], accB1[3], accB2[3];
        #pragma unroll
        for (int q = 0; q < 3; q++) {
            accJ0[q] = 0ull; accJ1[q] = 0ull;
            accB0[q] = 0ull; accB1[q] = 0ull; accB2[q] = 0ull;
        }

        // ---- inner reduction over hidden units, 4 at a time ----
        for (int t = 0; t < HIDN / 4; t++) {
            const int j0 = 4 * t;

            // Stage 1: batch table loads
            float4 A[4]; float2 U[4]; u64 w01[4], w23[4], w45[4];
            #pragma unroll
            for (int q = 0; q < 4; q++) {
                A[q] = tAct[j0 + q];
                U[q] = tU[j0 + q];
                ulonglong2 wp = tW[j0 + q];
                w01[q] = wp.x; w23[q] = wp.y;
                w45[q] = tW45[j0 + q];
            }

            // Stage 2: 4 independent activation chains + broadcasts
            u64 bdu0[4], bdu1[4], be00[4], be01[4], be11[4];
            #pragma unroll
            for (int q = 0; q < 4; q++) {
                float a   = fmaf(z0, A[q].x, fmaf(z1, A[q].y, A[q].z));
                float sig = __fdividef(1.f, 1.f + __expf(-a));
                float t1  = sig * (1.f - sig);
                float d   = fmaf(a, t1, sig);                        // swish'
                float e   = t1 * fmaf(a, fmaf(-2.f, sig, 1.f), 2.f); // swish''
                bdu0[q] = bcast2(d * A[q].x);
                bdu1[q] = bcast2(d * A[q].y);
                be00[q] = bcast2(e * A[q].w);
                be01[q] = bcast2(e * U[q].x);
                be11[q] = bcast2(e * U[q].y);
            }

            // Stage 3: packed rank-1 accumulations (15 FFMA2 per j)
            #pragma unroll
            for (int q = 0; q < 4; q++) {
                ffma2(accJ0[0], w01[q], bdu0[q]);
                ffma2(accJ0[1], w23[q], bdu0[q]);
                ffma2(accJ0[2], w45[q], bdu0[q]);
                ffma2(accJ1[0], w01[q], bdu1[q]);
                ffma2(accJ1[1], w23[q], bdu1[q]);
                ffma2(accJ1[2], w45[q], bdu1[q]);
                ffma2(accB0[0], w01[q], be00[q]);
                ffma2(accB0[1], w23[q], be00[q]);
                ffma2(accB0[2], w45[q], be00[q]);
                ffma2(accB1[0], w01[q], be01[q]);
                ffma2(accB1[1], w23[q], be01[q]);
                ffma2(accB1[2], w45[q], be01[q]);
                ffma2(accB2[0], w01[q], be11[q]);
                ffma2(accB2[1], w23[q], be11[q]);
                ffma2(accB2[2], w45[q], be11[q]);
            }
        }

        // Unpack to scalar per-head moments (same layout/order as scalar ver.)
        float J[6][2];
        float Bm[6][3];
        #pragma unroll
        for (int q = 0; q < 3; q++) {
            float2 v;
            v = unpk(accJ0[q]); J[2*q][0]  = v.x; J[2*q+1][0]  = v.y;
            v = unpk(accJ1[q]); J[2*q][1]  = v.x; J[2*q+1][1]  = v.y;
            v = unpk(accB0[q]); Bm[2*q][0] = v.x; Bm[2*q+1][0] = v.y;
            v = unpk(accB1[q]); Bm[2*q][1] = v.x; Bm[2*q+1][1] = v.y;
            v = unpk(accB2[q]); Bm[2*q][2] = v.x; Bm[2*q+1][2] = v.y;
        }

        // ---- 2x2 geometry ----
        float g00 = 0.f, g01 = 0.f, g11 = 0.f;
        float Dg[2][2][2];
        #pragma unroll
        for (int k = 0; k < 2; k++)
            #pragma unroll
            for (int m = 0; m < 2; m++)
                #pragma unroll
                for (int l = 0; l < 2; l++)
                    Dg[k][m][l] = 0.f;

        #pragma unroll
        for (int i = 0; i < 6; i++) {
            g00 = fmaf(J[i][0], J[i][0], g00);
            g01 = fmaf(J[i][0], J[i][1], g01);
            g11 = fmaf(J[i][1], J[i][1], g11);
            #pragma unroll
            for (int k = 0; k < 2; k++)
                #pragma unroll
                for (int m = 0; m < 2; m++)
                    #pragma unroll
                    for (int l = 0; l < 2; l++)
                        Dg[k][m][l] += Bm[i][k + l] * J[i][m] + J[i][k] * Bm[i][m + l];
        }

        const float detg = fmaf(g00, g11, -g01 * g01);
        const float rin  = __fdividef(1.f, detg);
        float gi[2][2];
        gi[0][0] =  g11 * rin;
        gi[0][1] = -g01 * rin;
        gi[1][0] = -g01 * rin;
        gi[1][1] =  g00 * rin;

        float Ch[2][2][2];
        #pragma unroll
        for (int i = 0; i < 2; i++)
            #pragma unroll
            for (int k = 0; k < 2; k++)
                #pragma unroll
                for (int l = 0; l < 2; l++) {
                    float sacc = 0.f;
                    #pragma unroll
                    for (int m = 0; m < 2; m++)
                        sacc += gi[i][m] * (Dg[k][m][l] + Dg[l][m][k] - Dg[k][l][m]);
                    Ch[i][k][l] = 0.5f * sacc;
                }

        float drift[2];
        #pragma unroll
        for (int i = 0; i < 2; i++) {
            float sacc = 0.f;
            #pragma unroll
            for (int jj = 0; jj < 2; jj++)
                #pragma unroll
                for (int kk = 0; kk < 2; kk++)
                    sacc += gi[jj][kk] * Ch[i][jj][kk];
            drift[i] = 0.5f * sacc;
        }

        const float dW0 = sqdt * nz.x;
        const float dW1 = sqdt * nz.y;

        z0 += drift[0] + gi[0][0] * dW0 + gi[0][1] * dW1;
        z1 += drift[1] + gi[1][0] * dW0 + gi[1][1] * dW1;
    }

    // Final decoder heads at z
    float mu[3] = { bdmu[0], bdmu[1], bdmu[2] };
    float ls[3] = { bds[0],  bds[1],  bds[2]  };
    #pragma unroll 4
    for (int j = 0; j < HIDN; j++) {
        const float4 A = tAct[j];
        ulonglong2 wp = tW[j];
        float2 w01 = unpk(wp.x);
        float2 w23 = unpk(wp.y);
        float2 w45 = unpk(tW45[j]);
        float a   = fmaf(z0, A.x, fmaf(z1, A.y, A.z));
        float sig = __fdividef(1.f, 1.f + __expf(-a));
        float h   = a * sig;
        mu[0] = fmaf(h, w01.x, mu[0]);
        mu[1] = fmaf(h, w01.y, mu[1]);
        mu[2] = fmaf(h, w23.x, mu[2]);
        ls[0] = fmaf(h, w23.y, ls[0]);
        ls[1] = fmaf(h, w45.x, ls[1]);
        ls[2] = fmaf(h, w45.y, ls[2]);
    }

    // Outputs: z | mu_xz | log_sigma_xz | mu_zx | log_t_zx | mu_z | log_t_z
    out[2 * p + 0] = z0;
    out[2 * p + 1] = z1;
    out[2 * NP + 3 * p + 0] = mu[0];
    out[2 * NP + 3 * p + 1] = mu[1];
    out[2 * NP + 3 * p + 2] = mu[2];
    out[5 * NP + 3 * p + 0] = ls[0];
    out[5 * NP + 3 * p + 1] = ls[1];
    out[5 * NP + 3 * p + 2] = ls[2];
    out[11 * NP + 2 * p + 0] = b_muz[0];
    out[11 * NP + 2 * p + 1] = b_muz[1];
    out[13 * NP + p] = b_ltz[0];
}

extern "C" void kernel_launch(void* const* d_in, const int* in_sizes, int n_in,
                              void* d_out, int out_size)
{
    const float* x     = (const float*)d_in[0];
    const float* We1   = (const float*)d_in[1];
    const float* be1   = (const float*)d_in[2];
    const float* We2   = (const float*)d_in[3];
    const float* be2   = (const float*)d_in[4];
    const float* Wmu   = (const float*)d_in[5];
    const float* bmu   = (const float*)d_in[6];
    const float* Wlt   = (const float*)d_in[7];
    const float* blt   = (const float*)d_in[8];
    const float* Wd1   = (const float*)d_in[9];
    const float* bd1   = (const float*)d_in[10];
    const float* Wdmu  = (const float*)d_in[11];
    const float* bdmu  = (const float*)d_in[12];
    const float* Wds   = (const float*)d_in[13];
    const float* bds   = (const float*)d_in[14];
    const float* b_muz = (const float*)d_in[15];
    const float* b_ltz = (const float*)d_in[16];
    const float* noise = (const float*)d_in[17];
    float* out = (float*)d_out;

    const size_t smem = (size_t)(10800 + 128 * (HIDN + 1)) * sizeof(float); // ~94.9 KB
    cudaFuncSetAttribute(encoder_kernel,
                         cudaFuncAttributeMaxDynamicSharedMemorySize, (int)smem);

    encoder_kernel<<<NP / 128, 128, smem>>>(x, We1, be1, We2, be2,
                                            Wmu, bmu, Wlt, blt, out);
    sde_kernel<<<NP / 128, 128>>>(Wd1, bd1, Wdmu, bdmu, Wds, bds,
                                  b_muz, b_ltz, noise, out);
}